// round 16
// baseline (speedup 1.0000x reference)
#include <cuda_runtime.h>
#include <cuda_fp16.h>
#include <cstdint>

#define NNODES 50000
#define NREL   8
#define D      128
#define NSEG   (NREL * NNODES)      // 400000
#define MAXE   1700000
#define ROWS   128
#define NTHR   512

// -------- scratch (device globals; no allocation allowed) --------
__device__ int    g_head[NSEG];      // statically zero; self-cleaned by k_gath each run
__device__ int2   g_nxt[MAXE];       // (dst, next_edge+1) linked-list records
__device__ __half g_wh[(NREL + 1) * D * D];          // fp16 [W_0..W_7, root]
__device__ __half g_xh[(size_t)(NNODES + 128) * D];  // fp16 x (+pad)
__device__ __half g_aggh[(size_t)(NSEG + 128) * D];  // fp16 agg (+pad)

// -------- merged setup + adjacency-chain build (head pre-zeroed by contract) --------
__global__ void k_prep(const float* __restrict__ W, const float* __restrict__ root,
                       const float* __restrict__ x, int n,
                       const int* __restrict__ ei_w, const int* __restrict__ et_w, int E) {
    __shared__ int s_st, s_stt;
    if (threadIdx.x == 0) {
        bool e64 = true, t64 = true;
        #pragma unroll
        for (int j = 1; j < 64; j += 2) {
            e64 = e64 && (ei_w[j] == 0);
            t64 = t64 && (et_w[j] == 0);
        }
        s_st  = e64 ? 2 : 1;
        s_stt = t64 ? 2 : 1;
    }
    __syncthreads();
    int st = s_st, stt = s_stt;

    int i = blockIdx.x * blockDim.x + threadIdx.x;
    int stride = gridDim.x * blockDim.x;

    const int nw = NREL * D * D;
    for (int j = i; j < nw + D * D; j += stride)
        g_wh[j] = __float2half(j < nw ? W[j] : root[j - nw]);
    int nx4 = n * D / 4;
    for (int j = i; j < nx4; j += stride) {
        float4 v = __ldg((const float4*)x + j);
        __half2* o = (__half2*)(g_xh + (size_t)j * 4);
        o[0] = __floats2half2_rn(v.x, v.y);
        o[1] = __floats2half2_rn(v.z, v.w);
    }
    // build per-(rel,node) linked chains (head guaranteed zero at entry)
    for (int j = i; j < E; j += stride) {
        int s = ei_w[(size_t)j * st];
        int d = ei_w[((size_t)E + j) * st];
        int t = et_w[(size_t)j * stt];
        int key = t * NNODES + s;
        if ((unsigned)key < NSEG) {
            int prev = atomicExch(&g_head[key], j + 1);
            g_nxt[j] = make_int2(d, prev);
        }
    }
}

// -------- gather+mean: half-warp per segment, chain walk --------
__device__ __forceinline__ void acc_h8(float* a, uint4 u) {
    float2 f0 = __half22float2(*(__half2*)&u.x);
    float2 f1 = __half22float2(*(__half2*)&u.y);
    float2 f2 = __half22float2(*(__half2*)&u.z);
    float2 f3 = __half22float2(*(__half2*)&u.w);
    a[0] += f0.x; a[1] += f0.y; a[2] += f1.x; a[3] += f1.y;
    a[4] += f2.x; a[5] += f2.y; a[6] += f3.x; a[7] += f3.y;
}

__global__ void __launch_bounds__(256)
k_gath() {
    int tid = threadIdx.x;
    int seg = (blockIdx.x * 256 + tid) >> 4;    // half-warp per segment
    int hl  = tid & 15;
    if (seg >= NSEG) return;

    int h = g_head[seg];
    g_head[seg] = 0;                  // self-clean for next graph replay

    float a[8] = {0.f, 0.f, 0.f, 0.f, 0.f, 0.f, 0.f, 0.f};
    int cnt = 0;
    while (h) {
        int2 rec = __ldg(&g_nxt[h - 1]);       // broadcast 8B load
        h = rec.y;                             // chain critical path
        uint4 u = __ldg((const uint4*)(g_xh + (size_t)rec.x * D) + hl);
        acc_h8(a, u);
        cnt++;
    }
    float inv = (cnt > 0) ? 1.0f / (float)cnt : 0.0f;
    uint4 pk;
    ((__half2*)&pk)[0] = __floats2half2_rn(a[0] * inv, a[1] * inv);
    ((__half2*)&pk)[1] = __floats2half2_rn(a[2] * inv, a[3] * inv);
    ((__half2*)&pk)[2] = __floats2half2_rn(a[4] * inv, a[5] * inv);
    ((__half2*)&pk)[3] = __floats2half2_rn(a[6] * inv, a[7] * inv);
    *((uint4*)(g_aggh + (size_t)seg * D) + hl) = pk;
}

// -------- dense fp16 MMA GEMM, double-buffered, ldmatrix fragment feed --------
__device__ __forceinline__ void mma_f16(float* c,
                                        unsigned a0, unsigned a1, unsigned a2, unsigned a3,
                                        unsigned b0, unsigned b1) {
    asm volatile(
        "mma.sync.aligned.m16n8k16.row.col.f32.f16.f16.f32 "
        "{%0,%1,%2,%3},{%4,%5,%6,%7},{%8,%9},{%0,%1,%2,%3};"
        : "+f"(c[0]), "+f"(c[1]), "+f"(c[2]), "+f"(c[3])
        : "r"(a0), "r"(a1), "r"(a2), "r"(a3), "r"(b0), "r"(b1));
}

__device__ __forceinline__ void ldsm_x4(unsigned& r0, unsigned& r1, unsigned& r2, unsigned& r3,
                                        uint32_t addr) {
    asm volatile("ldmatrix.sync.aligned.m8n8.x4.shared.b16 {%0,%1,%2,%3}, [%4];"
                 : "=r"(r0), "=r"(r1), "=r"(r2), "=r"(r3) : "r"(addr));
}

__device__ __forceinline__ void cp16(uint32_t sdst, const void* gsrc) {
    asm volatile("cp.async.cg.shared.global [%0], [%1], 16;" :: "r"(sdst), "l"(gsrc));
}

#define TILE_H    (128 * 136)            // halves per tile
#define GEMM_SMEM (4 * TILE_H * 2)       // A0,B0,A1,B1 = 139264 B

__global__ void __launch_bounds__(NTHR)
k_gemm(const float* __restrict__ bias, float* __restrict__ out, int n) {
    extern __shared__ __half smh[];

    int tid  = threadIdx.x;
    int lane = tid & 31;
    int warp = tid >> 5;
    int rowBase = blockIdx.x * ROWS;
    int gpr = lane >> 2;
    int tg  = lane & 3;
    int rowStrip = (warp & 7) * 16;
    int colBase  = (warp >> 3) * 64;

    float acc[8][4];
    #pragma unroll
    for (int t = 0; t < 8; t++)
        #pragma unroll
        for (int q = 0; q < 4; q++) acc[t][q] = 0.f;

    auto stage = [&](int buf, int s) {
        const __half* Ag = (s < NREL)
            ? (g_aggh + ((size_t)s * NNODES + rowBase) * D)
            : (g_xh + (size_t)rowBase * D);
        const __half* Bg = g_wh + (s << 14);
        __half* Asb = smh + buf * 2 * TILE_H;
        __half* Bsb = Asb + TILE_H;
        #pragma unroll
        for (int i = 0; i < 4; i++) {
            int idx = i * NTHR + tid;
            int r = idx >> 4, c = (idx & 15) * 8;
            cp16((uint32_t)__cvta_generic_to_shared(Asb + r * 136 + c), Ag + (size_t)r * D + c);
            cp16((uint32_t)__cvta_generic_to_shared(Bsb + r * 136 + c), Bg + r * D + c);
        }
        asm volatile("cp.async.commit_group;");
    };

    int aRow = rowStrip + (lane & 15);
    int aCol = (lane >> 4) * 8;
    int bsel = lane >> 3;
    int bRowInPair = (bsel >> 1) * 8 + (lane & 7);
    int bCol = (bsel & 1) * 8;

    stage(0, 0);

    #pragma unroll 1
    for (int s = 0; s < NREL + 1; s++) {
        if (s < NREL) {
            stage((s + 1) & 1, s + 1);
            asm volatile("cp.async.wait_group 1;" ::: "memory");
        } else {
            asm volatile("cp.async.wait_group 0;" ::: "memory");
        }
        __syncthreads();

        __half* Asb = smh + (s & 1) * 2 * TILE_H;
        __half* Bsb = Asb + TILE_H;

        uint32_t aAddr = (uint32_t)__cvta_generic_to_shared(Asb + aRow * 136 + aCol);
        uint32_t bAddr0 = (uint32_t)__cvta_generic_to_shared(
            Bsb + (colBase + bRowInPair) * 136 + bCol);

        #pragma unroll
        for (int kk = 0; kk < 8; kk++) {
            uint32_t kOff = kk * 32;
            unsigned a0, a1, a2, a3;
            ldsm_x4(a0, a1, a2, a3, aAddr + kOff);
            #pragma unroll
            for (int tp = 0; tp < 4; tp++) {
                unsigned b0, b1, b2, b3;
                ldsm_x4(b0, b1, b2, b3, bAddr0 + tp * (16 * 136 * 2) + kOff);
                mma_f16(acc[tp * 2],     a0, a1, a2, a3, b0, b1);
                mma_f16(acc[tp * 2 + 1], a0, a1, a2, a3, b2, b3);
            }
        }
        __syncthreads();
    }

    #pragma unroll
    for (int t = 0; t < 8; t++) {
        int col = colBase + t * 8 + tg * 2;
        float bv0 = __ldg(bias + col), bv1 = __ldg(bias + col + 1);
        int row0 = rowBase + rowStrip + gpr;
        int row1 = row0 + 8;
        if (row0 < n) {
            float2 v = make_float2(acc[t][0] + bv0, acc[t][1] + bv1);
            *(float2*)(out + (size_t)row0 * D + col) = v;
        }
        if (row1 < n) {
            float2 v = make_float2(acc[t][2] + bv0, acc[t][3] + bv1);
            *(float2*)(out + (size_t)row1 * D + col) = v;
        }
    }
}

extern "C" void kernel_launch(void* const* d_in, const int* in_sizes, int n_in,
                              void* d_out, int out_size) {
    const float* x    = (const float*)d_in[0];
    const int*   ei_w = (const int*)d_in[1];
    const int*   et_w = (const int*)d_in[2];
    const float* W    = (const float*)d_in[3];
    const float* root = (const float*)d_in[4];
    const float* bias = (const float*)d_in[5];
    float*       out  = (float*)d_out;

    int E = in_sizes[1] / 2;
    int n = in_sizes[0] / D;

    static bool attr_set = false;
    if (!attr_set) {
        cudaFuncSetAttribute(k_gemm, cudaFuncAttributeMaxDynamicSharedMemorySize, GEMM_SMEM);
        attr_set = true;
    }

    k_prep<<<3200, 512>>>(W, root, x, n, ei_w, et_w, E);
    k_gath<<<(NSEG * 16 + 255) / 256, 256>>>();
    k_gemm<<<(n + ROWS - 1) / ROWS, NTHR, GEMM_SMEM>>>(bias, out, n);
}

// round 17
// speedup vs baseline: 2.2558x; 2.2558x over previous
#include <cuda_runtime.h>
#include <cuda_fp16.h>
#include <cooperative_groups.h>
#include <cstdint>

namespace cg = cooperative_groups;

#define NNODES 50000
#define NREL   8
#define D      128
#define NSEG   (NREL * NNODES)      // 400000
#define MAXE   1700000
#define ROWS   128
#define NTHR   512

// -------- scratch (device globals; no allocation allowed) --------
__device__ int    g_deg[NSEG];       // statically zero; self-cleaned by k_css each run
__device__ int    g_off[NSEG + 1];
__device__ int    g_cur[NSEG];
__device__ int    g_bsum[512];
__device__ int    g_sorted[MAXE];
__device__ int    g_st_ei;
__device__ int    g_st_et;
__device__ __half g_wh[(NREL + 1) * D * D];          // fp16 [W_0..W_7, root]
__device__ __half g_xh[(size_t)(NNODES + 128) * D];  // fp16 x (+pad)
__device__ __half g_aggh[(size_t)(NSEG + 128) * D];  // fp16 agg (+pad)

// -------- merged setup + histogram (g_deg pre-zeroed by contract) --------
__global__ void k_prep(const float* __restrict__ W, const float* __restrict__ root,
                       const float* __restrict__ x, int n,
                       const int* __restrict__ ei_w, const int* __restrict__ et_w, int E) {
    __shared__ int s_st, s_stt;
    if (threadIdx.x == 0) {
        bool e64 = true, t64 = true;
        #pragma unroll
        for (int j = 1; j < 64; j += 2) {
            e64 = e64 && (ei_w[j] == 0);
            t64 = t64 && (et_w[j] == 0);
        }
        s_st  = e64 ? 2 : 1;
        s_stt = t64 ? 2 : 1;
        if (blockIdx.x == 0) { g_st_ei = s_st; g_st_et = s_stt; }
    }
    __syncthreads();
    int st = s_st, stt = s_stt;

    int i = blockIdx.x * blockDim.x + threadIdx.x;
    int stride = gridDim.x * blockDim.x;

    const int nw = NREL * D * D;
    for (int j = i; j < nw + D * D; j += stride)
        g_wh[j] = __float2half(j < nw ? W[j] : root[j - nw]);
    int nx4 = n * D / 4;
    for (int j = i; j < nx4; j += stride) {
        float4 v = __ldg((const float4*)x + j);
        __half2* o = (__half2*)(g_xh + (size_t)j * 4);
        o[0] = __floats2half2_rn(v.x, v.y);
        o[1] = __floats2half2_rn(v.z, v.w);
    }
    for (int j = i; j < E; j += stride) {
        int s = ei_w[(size_t)j * st];
        int t = et_w[(size_t)j * stt];
        int key = t * NNODES + s;
        if ((unsigned)key < NSEG) atomicAdd(&g_deg[key], 1);
    }
}

// block-wide exclusive scan via warp shuffles; 2 barriers. sh must hold 33 ints.
// On return: *total = block sum.
__device__ __forceinline__ int block_scan_excl(int v, int* sh, int tid, int* total) {
    int lane = tid & 31, w = tid >> 5;
    int incl = v;
    #pragma unroll
    for (int o = 1; o < 32; o <<= 1) {
        int t = __shfl_up_sync(0xffffffffu, incl, o);
        if (lane >= o) incl += t;
    }
    if (lane == 31) sh[w] = incl;
    __syncthreads();
    if (w == 0) {
        int s = sh[lane];
        #pragma unroll
        for (int o = 1; o < 32; o <<= 1) {
            int t = __shfl_up_sync(0xffffffffu, s, o);
            if (lane >= o) s += t;
        }
        sh[lane] = s;                // inclusive warp-sum prefix
    }
    __syncthreads();
    int woff = (w > 0) ? sh[w - 1] : 0;
    *total = sh[31];
    return woff + incl - v;
}

// -------- cooperative scan + scatter (zeroes g_deg as it consumes it) --------
__global__ void __launch_bounds__(1024)
k_css(const int* __restrict__ ei_w, const int* __restrict__ et_w, int E) {
    __shared__ int sh[33];
    __shared__ int s_base;
    int tid = threadIdx.x, b = blockIdx.x, nb = gridDim.x;
    int chunk = (NSEG + nb - 1) / nb;
    int lo = b * chunk;
    int hi = min(lo + chunk, NSEG);
    int carry = 0;

    for (int t0 = lo; t0 < hi; t0 += 1024) {
        int i = t0 + tid;
        int v = 0;
        if (i < hi) {
            v = g_deg[i];
            g_deg[i] = 0;            // self-clean for next graph replay
        }
        int tot;
        int ex = block_scan_excl(v, sh, tid, &tot);
        if (i < hi) g_off[i] = ex + carry;
        carry += tot;
        __syncthreads();             // sh reuse safe
    }
    if (tid == 0) g_bsum[b] = carry;
    cg::this_grid().sync();

    {
        int v2 = (tid < nb) ? g_bsum[tid] : 0;
        int tot;
        int ex = block_scan_excl(v2, sh, tid, &tot);
        if (tid == b) s_base = ex;
        __syncthreads();
    }
    int base = s_base;
    for (int t0 = lo; t0 < hi; t0 += 1024) {
        int i = t0 + tid;
        if (i < hi) {
            int o = g_off[i] + base;
            g_off[i] = o;
            g_cur[i] = o;
        }
    }
    if (b == 0 && tid == 0) g_off[NSEG] = E;
    cg::this_grid().sync();

    int st = g_st_ei, stt = g_st_et;
    for (int i = b * 1024 + tid; i < E; i += nb * 1024) {
        int s = ei_w[(size_t)i * st];
        int d = ei_w[((size_t)E + i) * st];
        int t = et_w[(size_t)i * stt];
        int key = t * NNODES + s;
        if ((unsigned)key < NSEG) {
            int pos = atomicAdd(&g_cur[key], 1);
            if ((unsigned)pos < MAXE) g_sorted[pos] = d;
        }
    }
}

// -------- gather+mean: half-warp per segment --------
__device__ __forceinline__ void acc_h8(float* a, uint4 u) {
    float2 f0 = __half22float2(*(__half2*)&u.x);
    float2 f1 = __half22float2(*(__half2*)&u.y);
    float2 f2 = __half22float2(*(__half2*)&u.z);
    float2 f3 = __half22float2(*(__half2*)&u.w);
    a[0] += f0.x; a[1] += f0.y; a[2] += f1.x; a[3] += f1.y;
    a[4] += f2.x; a[5] += f2.y; a[6] += f3.x; a[7] += f3.y;
}

__global__ void __launch_bounds__(256)
k_gath() {
    int tid = threadIdx.x;
    int seg = (blockIdx.x * 256 + tid) >> 4;
    int hl  = tid & 15;
    if (seg >= NSEG) return;
    int e0  = g_off[seg];
    int cnt = g_off[seg + 1] - e0;

    float a[8] = {0.f, 0.f, 0.f, 0.f, 0.f, 0.f, 0.f, 0.f};
    int j = 0;
    for (; j + 3 < cnt; j += 4) {
        int d0 = __ldg(&g_sorted[e0 + j]);
        int d1 = __ldg(&g_sorted[e0 + j + 1]);
        int d2 = __ldg(&g_sorted[e0 + j + 2]);
        int d3 = __ldg(&g_sorted[e0 + j + 3]);
        uint4 u0 = __ldg((const uint4*)(g_xh + (size_t)d0 * D) + hl);
        uint4 u1 = __ldg((const uint4*)(g_xh + (size_t)d1 * D) + hl);
        uint4 u2 = __ldg((const uint4*)(g_xh + (size_t)d2 * D) + hl);
        uint4 u3 = __ldg((const uint4*)(g_xh + (size_t)d3 * D) + hl);
        acc_h8(a, u0); acc_h8(a, u1); acc_h8(a, u2); acc_h8(a, u3);
    }
    for (; j < cnt; j++) {
        int d0 = __ldg(&g_sorted[e0 + j]);
        uint4 u0 = __ldg((const uint4*)(g_xh + (size_t)d0 * D) + hl);
        acc_h8(a, u0);
    }
    float inv = (cnt > 0) ? 1.0f / (float)cnt : 0.0f;
    uint4 pk;
    ((__half2*)&pk)[0] = __floats2half2_rn(a[0] * inv, a[1] * inv);
    ((__half2*)&pk)[1] = __floats2half2_rn(a[2] * inv, a[3] * inv);
    ((__half2*)&pk)[2] = __floats2half2_rn(a[4] * inv, a[5] * inv);
    ((__half2*)&pk)[3] = __floats2half2_rn(a[6] * inv, a[7] * inv);
    *((uint4*)(g_aggh + (size_t)seg * D) + hl) = pk;
}

// -------- dense fp16 MMA GEMM, double-buffered, ldmatrix fragment feed --------
__device__ __forceinline__ void mma_f16(float* c,
                                        unsigned a0, unsigned a1, unsigned a2, unsigned a3,
                                        unsigned b0, unsigned b1) {
    asm volatile(
        "mma.sync.aligned.m16n8k16.row.col.f32.f16.f16.f32 "
        "{%0,%1,%2,%3},{%4,%5,%6,%7},{%8,%9},{%0,%1,%2,%3};"
        : "+f"(c[0]), "+f"(c[1]), "+f"(c[2]), "+f"(c[3])
        : "r"(a0), "r"(a1), "r"(a2), "r"(a3), "r"(b0), "r"(b1));
}

__device__ __forceinline__ void ldsm_x4(unsigned& r0, unsigned& r1, unsigned& r2, unsigned& r3,
                                        uint32_t addr) {
    asm volatile("ldmatrix.sync.aligned.m8n8.x4.shared.b16 {%0,%1,%2,%3}, [%4];"
                 : "=r"(r0), "=r"(r1), "=r"(r2), "=r"(r3) : "r"(addr));
}

__device__ __forceinline__ void cp16(uint32_t sdst, const void* gsrc) {
    asm volatile("cp.async.cg.shared.global [%0], [%1], 16;" :: "r"(sdst), "l"(gsrc));
}

#define TILE_H    (128 * 136)            // halves per tile
#define GEMM_SMEM (4 * TILE_H * 2)       // A0,B0,A1,B1 = 139264 B

__global__ void __launch_bounds__(NTHR)
k_gemm(const float* __restrict__ bias, float* __restrict__ out, int n) {
    extern __shared__ __half smh[];

    int tid  = threadIdx.x;
    int lane = tid & 31;
    int warp = tid >> 5;
    int rowBase = blockIdx.x * ROWS;
    int gpr = lane >> 2;
    int tg  = lane & 3;
    int rowStrip = (warp & 7) * 16;
    int colBase  = (warp >> 3) * 64;

    float acc[8][4];
    #pragma unroll
    for (int t = 0; t < 8; t++)
        #pragma unroll
        for (int q = 0; q < 4; q++) acc[t][q] = 0.f;

    auto stage = [&](int buf, int s) {
        const __half* Ag = (s < NREL)
            ? (g_aggh + ((size_t)s * NNODES + rowBase) * D)
            : (g_xh + (size_t)rowBase * D);
        const __half* Bg = g_wh + (s << 14);
        __half* Asb = smh + buf * 2 * TILE_H;
        __half* Bsb = Asb + TILE_H;
        #pragma unroll
        for (int i = 0; i < 4; i++) {
            int idx = i * NTHR + tid;
            int r = idx >> 4, c = (idx & 15) * 8;
            cp16((uint32_t)__cvta_generic_to_shared(Asb + r * 136 + c), Ag + (size_t)r * D + c);
            cp16((uint32_t)__cvta_generic_to_shared(Bsb + r * 136 + c), Bg + r * D + c);
        }
        asm volatile("cp.async.commit_group;");
    };

    int aRow = rowStrip + (lane & 15);
    int aCol = (lane >> 4) * 8;
    int bsel = lane >> 3;
    int bRowInPair = (bsel >> 1) * 8 + (lane & 7);
    int bCol = (bsel & 1) * 8;

    stage(0, 0);

    #pragma unroll 1
    for (int s = 0; s < NREL + 1; s++) {
        if (s < NREL) {
            stage((s + 1) & 1, s + 1);
            asm volatile("cp.async.wait_group 1;" ::: "memory");
        } else {
            asm volatile("cp.async.wait_group 0;" ::: "memory");
        }
        __syncthreads();

        __half* Asb = smh + (s & 1) * 2 * TILE_H;
        __half* Bsb = Asb + TILE_H;

        uint32_t aAddr = (uint32_t)__cvta_generic_to_shared(Asb + aRow * 136 + aCol);
        uint32_t bAddr0 = (uint32_t)__cvta_generic_to_shared(
            Bsb + (colBase + bRowInPair) * 136 + bCol);

        #pragma unroll
        for (int kk = 0; kk < 8; kk++) {
            uint32_t kOff = kk * 32;
            unsigned a0, a1, a2, a3;
            ldsm_x4(a0, a1, a2, a3, aAddr + kOff);
            #pragma unroll
            for (int tp = 0; tp < 4; tp++) {
                unsigned b0, b1, b2, b3;
                ldsm_x4(b0, b1, b2, b3, bAddr0 + tp * (16 * 136 * 2) + kOff);
                mma_f16(acc[tp * 2],     a0, a1, a2, a3, b0, b1);
                mma_f16(acc[tp * 2 + 1], a0, a1, a2, a3, b2, b3);
            }
        }
        __syncthreads();
    }

    #pragma unroll
    for (int t = 0; t < 8; t++) {
        int col = colBase + t * 8 + tg * 2;
        float bv0 = __ldg(bias + col), bv1 = __ldg(bias + col + 1);
        int row0 = rowBase + rowStrip + gpr;
        int row1 = row0 + 8;
        if (row0 < n) {
            float2 v = make_float2(acc[t][0] + bv0, acc[t][1] + bv1);
            *(float2*)(out + (size_t)row0 * D + col) = v;
        }
        if (row1 < n) {
            float2 v = make_float2(acc[t][2] + bv0, acc[t][3] + bv1);
            *(float2*)(out + (size_t)row1 * D + col) = v;
        }
    }
}

extern "C" void kernel_launch(void* const* d_in, const int* in_sizes, int n_in,
                              void* d_out, int out_size) {
    const float* x    = (const float*)d_in[0];
    const int*   ei_w = (const int*)d_in[1];
    const int*   et_w = (const int*)d_in[2];
    const float* W    = (const float*)d_in[3];
    const float* root = (const float*)d_in[4];
    const float* bias = (const float*)d_in[5];
    float*       out  = (float*)d_out;

    int E = in_sizes[1] / 2;
    int n = in_sizes[0] / D;

    static bool attr_set = false;
    if (!attr_set) {
        cudaFuncSetAttribute(k_gemm, cudaFuncAttributeMaxDynamicSharedMemorySize, GEMM_SMEM);
        attr_set = true;
    }

    k_prep<<<3200, 512>>>(W, root, x, n, ei_w, et_w, E);
    {
        const int* a0 = ei_w;
        const int* a1 = et_w;
        int       a2 = E;
        void* args[3] = { (void*)&a0, (void*)&a1, (void*)&a2 };
        cudaLaunchCooperativeKernel((void*)k_css, dim3(148), dim3(1024), args, 0, 0);
    }
    k_gath<<<(NSEG * 16 + 255) / 256, 256>>>();
    k_gemm<<<(n + ROWS - 1) / ROWS, NTHR, GEMM_SMEM>>>(bias, out, n);
}